// round 13
// baseline (speedup 1.0000x reference)
#include <cuda_runtime.h>
#include <stdint.h>

#define NBINS   29
#define BB      64
#define CC      4
#define QQ      32
#define DD      4096

#define THREADS 256
#define POS     4                  // int4 positions per thread: 1024/256
#define CSTRIDE (QQ * DD / 4)      // channel stride in float4 units

#define HIST_WORDS (NBINS * THREADS)   // 29*256 u32 = 29.7 KB

__device__ __forceinline__ void proc_elem(float x, int m, uint8_t* col) {
    // bit-exact: ((x + 1.00001) / 2 * 28) trunc -> int.
    // (x+c)*0.5 is exact, so ((x+c)*0.5)*28 == (x+c)*14 with identical rounding.
    float t = __fmul_rn(__fadd_rn(x, 1.00001f), 14.0f);
    unsigned bin = (unsigned)__float2int_rz(t);
    bin = min(bin, 28u);                 // memory-safety clamp only
    if (m) col[bin << 10] += (uint8_t)1; // stride 1024 B per bin
}

__global__ __launch_bounds__(THREADS, 6)
void CountHistogram_kernel(const float* __restrict__ simmat,
                           const int* __restrict__ mask,
                           float* __restrict__ out) {
    // Channel-fused, conflict-free layout:
    //   byte = bin*1024 + tid*4 + c  ->  word = bin*256 + tid, bank = tid%32.
    // Each thread owns 4 independent u8 RMW chains (one per channel) and
    // serves all 4 channels of its int4 positions -> mask loaded ONCE.
    __shared__ uint32_t histw[HIST_WORDS];
    __shared__ uint32_t part[POS][NBINS][2];   // stage-1 partials (1 KB)
    uint8_t* hist8 = (uint8_t*)histw;

    const int tid = threadIdx.x;
    const int bq  = blockIdx.x;            // 0 .. B*Q-1
    const int b   = bq / QQ;
    const int q   = bq % QQ;

    #pragma unroll
    for (int i = 0; i < NBINS; i++) histw[i * THREADS + tid] = 0u;
    __syncthreads();

    const float4* srow = (const float4*)simmat +
                         ((size_t)b * CC * QQ + q) * (DD / 4);   // channel 0
    const int4*   mrow = (const int4*)mask +
                         ((size_t)b * QQ + q) * (DD / 4);

    // Front-batched loads: 4 mask + 16 sim LDG.128 per thread.
    int4   m4[POS];
    float4 s[POS][CC];
    #pragma unroll
    for (int k = 0; k < POS; k++) m4[k] = mrow[tid + k * THREADS];
    #pragma unroll
    for (int k = 0; k < POS; k++)
        #pragma unroll
        for (int c = 0; c < CC; c++)
            s[k][c] = srow[tid + k * THREADS + c * CSTRIDE];

    uint8_t* col = hist8 + 4 * tid;        // channel c uses col + c

    #pragma unroll
    for (int k = 0; k < POS; k++) {
        #pragma unroll
        for (int c = 0; c < CC; c++) proc_elem(s[k][c].x, m4[k].x, col + c);
        #pragma unroll
        for (int c = 0; c < CC; c++) proc_elem(s[k][c].y, m4[k].y, col + c);
        #pragma unroll
        for (int c = 0; c < CC; c++) proc_elem(s[k][c].z, m4[k].z, col + c);
        #pragma unroll
        for (int c = 0; c < CC; c++) proc_elem(s[k][c].w, m4[k].w, col + c);
    }
    __syncthreads();

    // Stage 1: (bin, quarter) -> sum 64 words into 2x(2xu16) accumulators.
    // lo holds channels 0,2; hi holds channels 1,3. Max field = 64*16 = 1024.
    // Lane-rotated index: bank = (i+tid)%32, distinct across warp lanes.
    if (tid < POS * NBINS) {
        const int bin = tid % NBINS;
        const int qq  = tid / NBINS;
        const uint32_t* base = histw + bin * THREADS + qq * 64;
        uint32_t lo = 0u, hi = 0u;
        #pragma unroll 8
        for (int i = 0; i < 64; i++) {
            const int j = (i + tid) & 63;
            uint32_t w = base[j];
            lo += w & 0x00FF00FFu;
            hi += (w >> 8) & 0x00FF00FFu;
        }
        part[qq][bin][0] = lo;
        part[qq][bin][1] = hi;
    }
    __syncthreads();

    // Stage 2: combine 4 quarters, extract this channel's u16 field.
    if (tid < CC * NBINS) {
        const int co  = tid / NBINS;
        const int bin = tid % NBINS;
        const int sel = co & 1;            // 0 -> lo word, 1 -> hi word
        const int sh  = (co >> 1) * 16;    // 0 -> low16, 1 -> high16
        unsigned sum = 0u;
        #pragma unroll
        for (int qq = 0; qq < POS; qq++)
            sum += (part[qq][bin][sel] >> sh) & 0xFFFFu;
        out[((((size_t)b * CC + co) * QQ + q) * NBINS) + bin] = (float)sum;
    }
}

extern "C" void kernel_launch(void* const* d_in, const int* in_sizes, int n_in,
                              void* d_out, int out_size) {
    const float* simmat = (const float*)d_in[0];
    const int*   mask   = (const int*)d_in[1];
    float*       out    = (float*)d_out;
    (void)in_sizes; (void)n_in; (void)out_size;

    dim3 grid(BB * QQ);     // 2048 blocks, one per (b, q)
    dim3 block(THREADS);
    CountHistogram_kernel<<<grid, block>>>(simmat, mask, out);
}